// round 14
// baseline (speedup 1.0000x reference)
#include <cuda_runtime.h>

#define BB 64
#define NN 4096
#define DD 129
#define EPSV 1e-7f
#define SUBS 16         // blocks per batch
#define BPW 32          // batches per wave
#define WAVES 2
#define PTSB 256        // points per block
#define NW 8            // warps per block

#define PF_L1(p) asm volatile("prefetch.global.L1 [%0];" :: "l"(p))

__device__ float g_spart[BB * SUBS * DD];
__device__ float g_varpart[BB * SUBS];
__device__ int g_cnt1[BB];
__device__ int g_cnt2[BB];

__global__ void init_kernel() {
    int t = threadIdx.x;
    if (t < BB) { g_cnt1[t] = 0; g_cnt2[t] = 0; }
}

// Warp-level block reduce: 2 block barriers. Result in all threads.
__device__ __forceinline__ float block_reduce_w(float v, float* s8, int w, int l) {
#pragma unroll
    for (int o = 16; o > 0; o >>= 1) v += __shfl_xor_sync(0xffffffffu, v, o);
    if (l == 0) s8[w] = v;
    __syncthreads();
    float r = 0.f;
#pragma unroll
    for (int i = 0; i < NW; i++) r += s8[i];
    __syncthreads();
    return r;
}

// Reduce 4 per-lane accumulators across the warp in 6 shuffles.
// Returns: lane l holds the 32-lane total of p[l&3].
__device__ __forceinline__ float reduce4(float p0, float p1, float p2, float p3,
                                         int l) {
    float v01 = (l & 1) ? p1 : p0;
    float o01 = (l & 1) ? p0 : p1;
    v01 += __shfl_xor_sync(0xffffffffu, o01, 1);
    float v23 = (l & 1) ? p3 : p2;
    float o23 = (l & 1) ? p2 : p3;
    v23 += __shfl_xor_sync(0xffffffffu, o23, 1);
    float v = (l & 2) ? v23 : v01;
    float o = (l & 2) ? v01 : v23;
    v += __shfl_xor_sync(0xffffffffu, o, 2);
    v += __shfl_xor_sync(0xffffffffu, v, 4);
    v += __shfl_xor_sync(0xffffffffu, v, 8);
    v += __shfl_xor_sync(0xffffffffu, v, 16);
    return v;
}

__device__ __forceinline__ float fast_acosh(float alpha) {
    return __logf(alpha + sqrtf((alpha - 1.f) * (alpha + 1.f)));
}

__global__ __launch_bounds__(256, 4) void fused_kernel(
    const float* __restrict__ x, const float* __restrict__ bias,
    const float* __restrict__ weight, float* __restrict__ out) {
    __shared__ float sbuf[NW * DD];   // phase-1 warp-private staging rows
    __shared__ float s8[NW];          // warp-reduce scratch
    __shared__ float4 s4[PTSB];       // (vs, q-vs*a, q, raw2) per point
    __shared__ float smu[DD], sbm[DD];
    __shared__ float sScal;

    int tid = threadIdx.x, w = tid >> 5, l = tid & 31;
    int bid = blockIdx.x;
    int sub = bid & (SUBS - 1);
    int bgrp = bid >> 4;   // 0..31

    // bias point on manifold (wave-invariant)
    float bias_v = (tid >= 1 && tid < DD) ? bias[tid - 1] : 0.f;
    float nb2 = block_reduce_w(bias_v * bias_v, s8, w, l);
    float nb = sqrtf(fmaxf(nb2, EPSV));
    float sclb = sinhf(nb) / nb;
    float bmv = (tid == 0) ? coshf(nb) : ((tid < DD) ? sclb * bias_v : 0.f);
    if (tid < DD) sbm[tid] = bmv;
    float sgn = (tid == 0) ? -1.f : 1.f;
    float bmr = (tid < DD) ? bmv : 0.f;
    float bb2 = block_reduce_w(sgn * bmr * bmr, s8, w, l);  // ldot(bm,bm)
    __syncthreads();

    // FLIPPED bm registers: beta = ldot(bm,x)
    float fbm_r[7], fbm_e[4];
#pragma unroll
    for (int i = 0; i < 7; i++) {
        int c = 4 * l - 3 + i;
        fbm_r[i] = (c > 0) ? sbm[c] : ((c == 0) ? -sbm[0] : 0.f);
    }
#pragma unroll
    for (int i = 0; i < 4; i++) fbm_e[i] = sbm[125 + i];

    for (int wave = 0; wave < WAVES; wave++) {
        int b = wave * BPW + bgrp;
        const float* xb = x + ((size_t)b * NN + (size_t)sub * PTSB) * DD;
        float* ob = out + ((size_t)b * NN + (size_t)sub * PTSB) * DD;

        float b_r[8];   // per-lane beta cache (point l&3 of group m)

        // ---- Phase 1: raw sum over 256 points + beta per point ----
        for (int i = l; i < DD; i += 32) sbuf[w * DD + i] = 0.f;
        __syncwarp();
        {
            float acc_r[7] = {0, 0, 0, 0, 0, 0, 0};
            float acc_e[4] = {0, 0, 0, 0};
#pragma unroll
            for (int m = 0; m < 8; m++) {
                int g = w + NW * m;
                const float4* p4 = (const float4*)(xb + (size_t)g * 4 * DD);
                if (m < 7) {   // prefetch next group into L1
                    const float4* pn = p4 + (size_t)NW * DD;
#pragma unroll
                    for (int k = 0; k < 4; k++) PF_L1(pn + l + 32 * k);
                    PF_L1(pn + 128);
                }
                float4 v[4];
#pragma unroll
                for (int k = 0; k < 4; k++) v[k] = p4[l + 32 * k];
                float4 ve = p4[128];
                float pb[4] = {0, 0, 0, 0};
#pragma unroll
                for (int k = 0; k < 4; k++) {
                    float xr0[4] = {v[k].x, v[k].y, v[k].z, v[k].w};
#pragma unroll
                    for (int j = 0; j < 4; j++) {
                        float xv = xr0[j];
                        if (l == 0 && j < k) {
                            int i = 4 - k + j;
                            acc_e[i] += xv;
                            pb[k - 1] += fbm_e[i] * xv;
                        } else {
                            int i = j - k + 3;
                            acc_r[i] += xv;
                            pb[k] += fbm_r[i] * xv;
                        }
                    }
                }
                if (l == 0) {
                    acc_e[0] += ve.x; acc_e[1] += ve.y;
                    acc_e[2] += ve.z; acc_e[3] += ve.w;
                    pb[3] += fbm_e[0] * ve.x + fbm_e[1] * ve.y +
                             fbm_e[2] * ve.z + fbm_e[3] * ve.w;
                }
                b_r[m] = reduce4(pb[0], pb[1], pb[2], pb[3], l);
            }
#pragma unroll
            for (int i = 0; i < 7; i++) {
                int c = 4 * l - 3 + i;
                if (c >= 0) sbuf[w * DD + c] += acc_r[i];
                __syncwarp();
            }
            if (l == 0) {
#pragma unroll
                for (int i = 0; i < 4; i++) sbuf[w * DD + 125 + i] += acc_e[i];
            }
        }
        __syncthreads();
        if (tid < DD) {
            float s = 0.f;
#pragma unroll
            for (int w2 = 0; w2 < NW; w2++) s += sbuf[w2 * DD + tid];
            g_spart[(b * SUBS + sub) * DD + tid] = s;
        }
        __threadfence();
        __syncthreads();
        if (tid == 0) {
            atomicAdd(&g_cnt1[b], 1);
            while (atomicAdd(&g_cnt1[b], 0) < SUBS) __nanosleep(32);
            __threadfence();
        }
        __syncthreads();

        // ---- mu + per-batch Lorentz scalars ----
        float sv = 0.f;
        if (tid < DD) {
#pragma unroll
            for (int s2 = 0; s2 < SUBS; s2++)
                sv += __ldcg(&g_spart[(b * SUBS + s2) * DD + tid]);
        }
        float r = block_reduce_w(-sgn * sv * sv, s8, w, l);  // -ldot(s,s)
        float inv = rsqrtf(fmaxf(r, EPSV));
        float mv = sv * inv;
        if (tid < DD) smu[tid] = mv;
        float lmm = block_reduce_w(sgn * mv * mv, s8, w, l);
        float lmb = block_reduce_w(sgn * mv * bmr, s8, w, l);
        float lkdi = 1.f / (1.f - lmb);
        float lww = lmm + 2.f * lmb + bb2;

        // FLIPPED mu registers: a = -ldot(mu,x)
        float fmu_r[7], fmu_e[4];
#pragma unroll
        for (int i = 0; i < 7; i++) {
            int c = 4 * l - 3 + i;
            fmu_r[i] = (c > 0) ? -smu[c] : ((c == 0) ? smu[0] : 0.f);
        }
#pragma unroll
        for (int i = 0; i < 4; i++) fmu_e[i] = -smu[125 + i];

        // ---- Phase 2: a per point + varsum + sc-independent coef parts ----
        float vloc = 0.f;
#pragma unroll
        for (int m = 0; m < 8; m++) {
            int g = w + NW * m;
            const float4* p4 = (const float4*)(xb + (size_t)g * 4 * DD);
            if (m < 7) {
                const float4* pn = p4 + (size_t)NW * DD;
#pragma unroll
                for (int k = 0; k < 4; k++) PF_L1(pn + l + 32 * k);
                PF_L1(pn + 128);
            }
            float4 v[4];
#pragma unroll
            for (int k = 0; k < 4; k++) v[k] = p4[l + 32 * k];
            float4 ve = p4[128];
            float pa[4] = {0, 0, 0, 0};
#pragma unroll
            for (int k = 0; k < 4; k++) {
                float xr0[4] = {v[k].x, v[k].y, v[k].z, v[k].w};
#pragma unroll
                for (int j = 0; j < 4; j++) {
                    float xv = xr0[j];
                    if (l == 0 && j < k) pa[k - 1] += fmu_e[4 - k + j] * xv;
                    else                 pa[k] += fmu_r[j - k + 3] * xv;
                }
            }
            if (l == 0) {
                pa[3] += fmu_e[0] * ve.x + fmu_e[1] * ve.y +
                         fmu_e[2] * ve.z + fmu_e[3] * ve.w;
            }
            float pav = reduce4(pa[0], pa[1], pa[2], pa[3], l);
            float alpha = fmaxf(pav, 1.f + EPSV);
            float d = fast_acosh(alpha);
            float dd = d * d;
            dd += __shfl_xor_sync(0xffffffffu, dd, 1);
            dd += __shfl_xor_sync(0xffffffffu, dd, 2);
            if (l == 0) vloc += dd;
            // sc-independent coefficient parts (point l&3, redundant per quad)
            float nu2 = 2.f * alpha * pav - alpha * alpha - 1.f;
            float nu = sqrtf(fmaxf(nu2, EPSV));
            float vsr = d / nu;
            float lbu = b_r[m] - alpha * lmb;
            float q = vsr * lbu * lkdi;
            float udot = (-pav - alpha * lmm) + lbu;
            float raw2 = vsr * vsr * nu2 + 2.f * vsr * q * udot + q * q * lww;
            if (l < 4) s4[4 * g + l] = make_float4(vsr, q - vsr * alpha, q, raw2);
        }
        if (l == 0) s8[w] = vloc;
        __syncthreads();
        if (tid == 0) {
            float s = 0.f;
#pragma unroll
            for (int w3 = 0; w3 < NW; w3++) s += s8[w3];
            g_varpart[b * SUBS + sub] = s;
            __threadfence();
            atomicAdd(&g_cnt2[b], 1);
            while (atomicAdd(&g_cnt2[b], 0) < SUBS) __nanosleep(32);
            __threadfence();
            float vs = 0.f;
#pragma unroll
            for (int s2 = 0; s2 < SUBS; s2++) vs += __ldcg(&g_varpart[b * SUBS + s2]);
            float var = vs / (float)NN;
            sScal = sqrtf(weight[0] / (var + 1e-6f));
        }
        __syncthreads();
        float sc = sScal;

        // unflipped mu/bm registers for the output combination
        float mu_r[7], bm_r[7], mu_e[4], bm_e[4];
#pragma unroll
        for (int i = 0; i < 7; i++) {
            int c = 4 * l - 3 + i;
            mu_r[i] = (c >= 0) ? smu[c] : 0.f;
            bm_r[i] = (c >= 0) ? sbm[c] : 0.f;
        }
#pragma unroll
        for (int i = 0; i < 4; i++) { mu_e[i] = smu[125 + i]; bm_e[i] = sbm[125 + i]; }

        // ---- Phase 3: short coefficient tail + stream x ----
#pragma unroll
        for (int m = 0; m < 8; m++) {
            int g = w + NW * m;
            const float4* p4 = (const float4*)(xb + (size_t)g * 4 * DD);
            float4* o4 = (float4*)(ob + (size_t)g * 4 * DD);
            if (m < 7) {
                const float4* pn = p4 + (size_t)NW * DD;
#pragma unroll
                for (int k = 0; k < 4; k++) PF_L1(pn + l + 32 * k);
                PF_L1(pn + 128);
            }

            float4 c4 = s4[4 * g + (l & 3)];
            float nn2 = sc * sc * c4.w;
            float nnv = sqrtf(fmaxf(nn2, EPSV));
            float e = __expf(nnv);
            float ei = __expf(-nnv);
            float chv = 0.5f * (e + ei);
            float shnv = 0.5f * (e - ei) / nnv;
            float s3 = shnv * sc;
            float cxv = s3 * c4.x;
            float cmv = s3 * c4.y;
            float cbv = chv + s3 * c4.z;

            float cx[4], cm[4], cb[4];
#pragma unroll
            for (int k = 0; k < 4; k++) {
                cx[k] = __shfl_sync(0xffffffffu, cxv, k);
                cm[k] = __shfl_sync(0xffffffffu, cmv, k);
                cb[k] = __shfl_sync(0xffffffffu, cbv, k);
            }
#pragma unroll
            for (int k = 0; k < 4; k++) {
                float4 v = __ldcs(&p4[l + 32 * k]);
                float xr0[4] = {v.x, v.y, v.z, v.w};
                float orr[4];
#pragma unroll
                for (int j = 0; j < 4; j++) {
                    if (l == 0 && j < k) {
                        int i = 4 - k + j, n = k - 1;
                        orr[j] = cx[n] * xr0[j] + cm[n] * mu_e[i] + cb[n] * bm_e[i];
                    } else {
                        int i = j - k + 3;
                        orr[j] = cx[k] * xr0[j] + cm[k] * mu_r[i] + cb[k] * bm_r[i];
                    }
                }
                __stcs(&o4[l + 32 * k], make_float4(orr[0], orr[1], orr[2], orr[3]));
            }
            if (l == 0) {
                float4 v = __ldcs(&p4[128]);
                float xe0[4] = {v.x, v.y, v.z, v.w};
                float orr[4];
#pragma unroll
                for (int j = 0; j < 4; j++)
                    orr[j] = cx[3] * xe0[j] + cm[3] * mu_e[j] + cb[3] * bm_e[j];
                __stcs(&o4[128], make_float4(orr[0], orr[1], orr[2], orr[3]));
            }
        }
        __syncthreads();  // protect s4/sbuf reuse across waves
    }
}

extern "C" void kernel_launch(void* const* d_in, const int* in_sizes, int n_in,
                              void* d_out, int out_size) {
    const float* x = (const float*)d_in[0];
    const float* bias = (const float*)d_in[1];
    const float* weight = (const float*)d_in[2];
    float* out = (float*)d_out;

    init_kernel<<<1, 128>>>();
    fused_kernel<<<512, 256>>>(x, bias, weight, out);
}

// round 15
// speedup vs baseline: 1.0521x; 1.0521x over previous
#include <cuda_runtime.h>

#define BB 64
#define NN 4096
#define DD 129
#define EPSV 1e-7f
#define SUBS 16         // blocks per batch
#define BPW 32          // batches per wave
#define WAVES 2
#define PTSB 256        // points per block
#define NW 8            // warps per block

__device__ float g_spart[BB * SUBS * DD];
__device__ float g_varpart[BB * SUBS];
__device__ unsigned int g_cnt1[BB];   // monotonic epoch counters (never reset)
__device__ unsigned int g_cnt2[BB];

// Warp-level block reduce: 2 block barriers. Result in all threads.
__device__ __forceinline__ float block_reduce_w(float v, float* s8, int w, int l) {
#pragma unroll
    for (int o = 16; o > 0; o >>= 1) v += __shfl_xor_sync(0xffffffffu, v, o);
    if (l == 0) s8[w] = v;
    __syncthreads();
    float r = 0.f;
#pragma unroll
    for (int i = 0; i < NW; i++) r += s8[i];
    __syncthreads();
    return r;
}

// Reduce 4 per-lane accumulators across the warp in 6 shuffles.
// Returns: lane l holds the 32-lane total of p[l&3].
__device__ __forceinline__ float reduce4(float p0, float p1, float p2, float p3,
                                         int l) {
    float v01 = (l & 1) ? p1 : p0;
    float o01 = (l & 1) ? p0 : p1;
    v01 += __shfl_xor_sync(0xffffffffu, o01, 1);
    float v23 = (l & 1) ? p3 : p2;
    float o23 = (l & 1) ? p2 : p3;
    v23 += __shfl_xor_sync(0xffffffffu, o23, 1);
    float v = (l & 2) ? v23 : v01;
    float o = (l & 2) ? v01 : v23;
    v += __shfl_xor_sync(0xffffffffu, o, 2);
    v += __shfl_xor_sync(0xffffffffu, v, 4);
    v += __shfl_xor_sync(0xffffffffu, v, 8);
    v += __shfl_xor_sync(0xffffffffu, v, 16);
    return v;
}

__device__ __forceinline__ float fast_acosh(float alpha) {
    return __logf(alpha + sqrtf((alpha - 1.f) * (alpha + 1.f)));
}

// Epoch spin barrier: counters are monotonic across launches/replays
// (replays are stream-serialized, so per-launch epochs never interleave).
__device__ __forceinline__ void epoch_barrier(unsigned int* cnt) {
    unsigned int ticket = atomicAdd(cnt, 1u);
    unsigned int target = (ticket / SUBS + 1u) * SUBS;
    while (atomicAdd(cnt, 0u) < target) __nanosleep(32);
    __threadfence();
}

__global__ __launch_bounds__(256, 4) void fused_kernel(
    const float* __restrict__ x, const float* __restrict__ bias,
    const float* __restrict__ weight, float* __restrict__ out) {
    __shared__ float sbuf[NW * DD];   // phase-1 warp-private staging rows
    __shared__ float s8[NW];          // warp-reduce scratch
    __shared__ float4 s4[PTSB];       // (vs, q-vs*a, q, raw2) per point
    __shared__ float smu[DD], sbm[DD];
    __shared__ float sScal;

    int tid = threadIdx.x, w = tid >> 5, l = tid & 31;
    int bid = blockIdx.x;
    int sub = bid & (SUBS - 1);
    int bgrp = bid >> 4;   // 0..31

    // bias point on manifold (wave-invariant)
    float bias_v = (tid >= 1 && tid < DD) ? bias[tid - 1] : 0.f;
    float nb2 = block_reduce_w(bias_v * bias_v, s8, w, l);
    float nb = sqrtf(fmaxf(nb2, EPSV));
    float sclb = sinhf(nb) / nb;
    float bmv = (tid == 0) ? coshf(nb) : ((tid < DD) ? sclb * bias_v : 0.f);
    if (tid < DD) sbm[tid] = bmv;
    float sgn = (tid == 0) ? -1.f : 1.f;
    float bmr = (tid < DD) ? bmv : 0.f;
    float bb2 = block_reduce_w(sgn * bmr * bmr, s8, w, l);  // ldot(bm,bm)
    __syncthreads();

    // FLIPPED bm registers: beta = ldot(bm,x)
    float fbm_r[7], fbm_e[4];
#pragma unroll
    for (int i = 0; i < 7; i++) {
        int c = 4 * l - 3 + i;
        fbm_r[i] = (c > 0) ? sbm[c] : ((c == 0) ? -sbm[0] : 0.f);
    }
#pragma unroll
    for (int i = 0; i < 4; i++) fbm_e[i] = sbm[125 + i];

    for (int wave = 0; wave < WAVES; wave++) {
        int b = wave * BPW + bgrp;
        const float* xb = x + ((size_t)b * NN + (size_t)sub * PTSB) * DD;
        float* ob = out + ((size_t)b * NN + (size_t)sub * PTSB) * DD;

        float b_r[8];   // per-lane beta cache (point l&3 of group m)

        // ---- Phase 1: raw sum over 256 points + beta per point ----
        for (int i = l; i < DD; i += 32) sbuf[w * DD + i] = 0.f;
        __syncwarp();
        {
            float acc_r[7] = {0, 0, 0, 0, 0, 0, 0};
            float acc_e[4] = {0, 0, 0, 0};
#pragma unroll
            for (int m = 0; m < 8; m++) {
                int g = w + NW * m;
                const float4* p4 = (const float4*)(xb + (size_t)g * 4 * DD);
                float4 v[4];
#pragma unroll
                for (int k = 0; k < 4; k++) v[k] = p4[l + 32 * k];
                float4 ve = p4[128];
                float pb[4] = {0, 0, 0, 0};
#pragma unroll
                for (int k = 0; k < 4; k++) {
                    float xr0[4] = {v[k].x, v[k].y, v[k].z, v[k].w};
#pragma unroll
                    for (int j = 0; j < 4; j++) {
                        float xv = xr0[j];
                        if (l == 0 && j < k) {
                            int i = 4 - k + j;
                            acc_e[i] += xv;
                            pb[k - 1] += fbm_e[i] * xv;
                        } else {
                            int i = j - k + 3;
                            acc_r[i] += xv;
                            pb[k] += fbm_r[i] * xv;
                        }
                    }
                }
                if (l == 0) {
                    acc_e[0] += ve.x; acc_e[1] += ve.y;
                    acc_e[2] += ve.z; acc_e[3] += ve.w;
                    pb[3] += fbm_e[0] * ve.x + fbm_e[1] * ve.y +
                             fbm_e[2] * ve.z + fbm_e[3] * ve.w;
                }
                b_r[m] = reduce4(pb[0], pb[1], pb[2], pb[3], l);
            }
#pragma unroll
            for (int i = 0; i < 7; i++) {
                int c = 4 * l - 3 + i;
                if (c >= 0) sbuf[w * DD + c] += acc_r[i];
                __syncwarp();
            }
            if (l == 0) {
#pragma unroll
                for (int i = 0; i < 4; i++) sbuf[w * DD + 125 + i] += acc_e[i];
            }
        }
        __syncthreads();
        if (tid < DD) {
            float s = 0.f;
#pragma unroll
            for (int w2 = 0; w2 < NW; w2++) s += sbuf[w2 * DD + tid];
            g_spart[(b * SUBS + sub) * DD + tid] = s;
        }
        __threadfence();
        __syncthreads();
        if (tid == 0) epoch_barrier(&g_cnt1[b]);
        __syncthreads();

        // ---- mu + per-batch Lorentz scalars ----
        float sv = 0.f;
        if (tid < DD) {
#pragma unroll
            for (int s2 = 0; s2 < SUBS; s2++)
                sv += __ldcg(&g_spart[(b * SUBS + s2) * DD + tid]);
        }
        float r = block_reduce_w(-sgn * sv * sv, s8, w, l);  // -ldot(s,s)
        float inv = rsqrtf(fmaxf(r, EPSV));
        float mv = sv * inv;
        if (tid < DD) smu[tid] = mv;
        float lmm = block_reduce_w(sgn * mv * mv, s8, w, l);
        float lmb = block_reduce_w(sgn * mv * bmr, s8, w, l);
        float lkdi = 1.f / (1.f - lmb);
        float lww = lmm + 2.f * lmb + bb2;

        // FLIPPED mu registers: a = -ldot(mu,x)
        float fmu_r[7], fmu_e[4];
#pragma unroll
        for (int i = 0; i < 7; i++) {
            int c = 4 * l - 3 + i;
            fmu_r[i] = (c > 0) ? -smu[c] : ((c == 0) ? smu[0] : 0.f);
        }
#pragma unroll
        for (int i = 0; i < 4; i++) fmu_e[i] = -smu[125 + i];

        // ---- Phase 2: a per point + varsum + sc-independent coef parts ----
        float vloc = 0.f;
#pragma unroll
        for (int m = 0; m < 8; m++) {
            int g = w + NW * m;
            const float4* p4 = (const float4*)(xb + (size_t)g * 4 * DD);
            float4 v[4];
#pragma unroll
            for (int k = 0; k < 4; k++) v[k] = p4[l + 32 * k];
            float4 ve = p4[128];
            float pa[4] = {0, 0, 0, 0};
#pragma unroll
            for (int k = 0; k < 4; k++) {
                float xr0[4] = {v[k].x, v[k].y, v[k].z, v[k].w};
#pragma unroll
                for (int j = 0; j < 4; j++) {
                    float xv = xr0[j];
                    if (l == 0 && j < k) pa[k - 1] += fmu_e[4 - k + j] * xv;
                    else                 pa[k] += fmu_r[j - k + 3] * xv;
                }
            }
            if (l == 0) {
                pa[3] += fmu_e[0] * ve.x + fmu_e[1] * ve.y +
                         fmu_e[2] * ve.z + fmu_e[3] * ve.w;
            }
            float pav = reduce4(pa[0], pa[1], pa[2], pa[3], l);
            float alpha = fmaxf(pav, 1.f + EPSV);
            float d = fast_acosh(alpha);
            float dd = d * d;
            dd += __shfl_xor_sync(0xffffffffu, dd, 1);
            dd += __shfl_xor_sync(0xffffffffu, dd, 2);
            if (l == 0) vloc += dd;
            // sc-independent coefficient parts (point l&3, redundant per quad)
            float nu2 = 2.f * alpha * pav - alpha * alpha - 1.f;
            float nu = sqrtf(fmaxf(nu2, EPSV));
            float vsr = d / nu;
            float lbu = b_r[m] - alpha * lmb;
            float q = vsr * lbu * lkdi;
            float udot = (-pav - alpha * lmm) + lbu;
            float raw2 = vsr * vsr * nu2 + 2.f * vsr * q * udot + q * q * lww;
            if (l < 4) s4[4 * g + l] = make_float4(vsr, q - vsr * alpha, q, raw2);
        }
        if (l == 0) s8[w] = vloc;
        __syncthreads();
        if (tid == 0) {
            float s = 0.f;
#pragma unroll
            for (int w3 = 0; w3 < NW; w3++) s += s8[w3];
            g_varpart[b * SUBS + sub] = s;
            __threadfence();
            epoch_barrier(&g_cnt2[b]);
            float vs = 0.f;
#pragma unroll
            for (int s2 = 0; s2 < SUBS; s2++) vs += __ldcg(&g_varpart[b * SUBS + s2]);
            float var = vs / (float)NN;
            sScal = sqrtf(weight[0] / (var + 1e-6f));
        }
        __syncthreads();
        float sc = sScal;

        // unflipped mu/bm registers for the output combination
        float mu_r[7], bm_r[7], mu_e[4], bm_e[4];
#pragma unroll
        for (int i = 0; i < 7; i++) {
            int c = 4 * l - 3 + i;
            mu_r[i] = (c >= 0) ? smu[c] : 0.f;
            bm_r[i] = (c >= 0) ? sbm[c] : 0.f;
        }
#pragma unroll
        for (int i = 0; i < 4; i++) { mu_e[i] = smu[125 + i]; bm_e[i] = sbm[125 + i]; }

        // ---- Phase 3: short coefficient tail + stream x ----
#pragma unroll
        for (int m = 0; m < 8; m++) {
            int g = w + NW * m;
            const float4* p4 = (const float4*)(xb + (size_t)g * 4 * DD);
            float4* o4 = (float4*)(ob + (size_t)g * 4 * DD);

            float4 c4 = s4[4 * g + (l & 3)];
            float nn2 = sc * sc * c4.w;
            float nnv = sqrtf(fmaxf(nn2, EPSV));
            float e = __expf(nnv);
            float ei = __expf(-nnv);
            float chv = 0.5f * (e + ei);
            float shnv = 0.5f * (e - ei) / nnv;
            float s3 = shnv * sc;
            float cxv = s3 * c4.x;
            float cmv = s3 * c4.y;
            float cbv = chv + s3 * c4.z;

            float cx[4], cm[4], cb[4];
#pragma unroll
            for (int k = 0; k < 4; k++) {
                cx[k] = __shfl_sync(0xffffffffu, cxv, k);
                cm[k] = __shfl_sync(0xffffffffu, cmv, k);
                cb[k] = __shfl_sync(0xffffffffu, cbv, k);
            }
#pragma unroll
            for (int k = 0; k < 4; k++) {
                float4 v = __ldcs(&p4[l + 32 * k]);
                float xr0[4] = {v.x, v.y, v.z, v.w};
                float orr[4];
#pragma unroll
                for (int j = 0; j < 4; j++) {
                    if (l == 0 && j < k) {
                        int i = 4 - k + j, n = k - 1;
                        orr[j] = cx[n] * xr0[j] + cm[n] * mu_e[i] + cb[n] * bm_e[i];
                    } else {
                        int i = j - k + 3;
                        orr[j] = cx[k] * xr0[j] + cm[k] * mu_r[i] + cb[k] * bm_r[i];
                    }
                }
                __stcs(&o4[l + 32 * k], make_float4(orr[0], orr[1], orr[2], orr[3]));
            }
            if (l == 0) {
                float4 v = __ldcs(&p4[128]);
                float xe0[4] = {v.x, v.y, v.z, v.w};
                float orr[4];
#pragma unroll
                for (int j = 0; j < 4; j++)
                    orr[j] = cx[3] * xe0[j] + cm[3] * mu_e[j] + cb[3] * bm_e[j];
                __stcs(&o4[128], make_float4(orr[0], orr[1], orr[2], orr[3]));
            }
        }
        __syncthreads();  // protect s4/sbuf reuse across waves
    }
}

extern "C" void kernel_launch(void* const* d_in, const int* in_sizes, int n_in,
                              void* d_out, int out_size) {
    const float* x = (const float*)d_in[0];
    const float* bias = (const float*)d_in[1];
    const float* weight = (const float*)d_in[2];
    float* out = (float*)d_out;

    fused_kernel<<<512, 256>>>(x, bias, weight, out);
}